// round 1
// baseline (speedup 1.0000x reference)
#include <cuda_runtime.h>
#include <cstdint>

// ---------------------------------------------------------------------------
// PackedSirenExperts: out[b,m,o] over M=64 experts, B=8192, H=256, IN=OUT=3
//   h = sin(30*(x @ w0^T + b0)); 3x h = sin(30*(h @ wl^T + bl)); out = h@wf^T+bf
// Strategy (R1 baseline): fully fused per (expert, 64-row batch tile) CTA,
// fp32 CUDA-core GEMMs, h resident in SMEM (double buffered, transposed),
// weights pre-transposed into __device__ scratch for cp.async streaming.
// ---------------------------------------------------------------------------

namespace {
constexpr int Bdim = 8192;
constexpr int Mexp = 64;
constexpr int INd  = 3;
constexpr int Hd   = 256;
constexpr int OUTd = 3;

constexpr int BT      = 64;              // batch rows per CTA
constexpr int KT      = 32;              // k-chunk for weight staging
constexpr int NCHUNK  = Hd / KT;         // 8
constexpr int THREADS = 256;
constexpr int HPAD    = 68;              // h row stride (floats), pads bank conflicts
constexpr float W0F   = 30.0f;           // both first and hidden omega

constexpr int SMEM_FLOATS = 2 * Hd * HPAD + 2 * KT * Hd + BT * 4;
constexpr int SMEM_BYTES  = SMEM_FLOATS * 4;   // 205,824 B
}

// Scratch: transposed hidden weights wT[layer][m][i][o]  (50.3 MB)
__device__ float g_wT[3][Mexp][Hd][Hd];

// ---------------------------------------------------------------------------
// Weight transpose: src[m][o][i] (256x256 per expert) -> g_wT[layer][m][i][o]
// ---------------------------------------------------------------------------
__global__ void transpose_weights(const float* __restrict__ src, int layer) {
    __shared__ float tile[32][33];
    const int m  = blockIdx.z;
    const float* s = src + (size_t)m * Hd * Hd;
    float* d = &g_wT[layer][m][0][0];
    const int ox = blockIdx.x * 32;   // i tile base
    const int oy = blockIdx.y * 32;   // o tile base
    const int tx = threadIdx.x, ty = threadIdx.y;
#pragma unroll
    for (int r = ty; r < 32; r += 8)
        tile[r][tx] = s[(oy + r) * Hd + ox + tx];        // src[o=oy+r][i=ox+tx]
    __syncthreads();
#pragma unroll
    for (int r = ty; r < 32; r += 8)
        d[(ox + r) * Hd + oy + tx] = tile[tx][r];        // dst[i=ox+r][o=oy+tx]
}

// ---------------------------------------------------------------------------
// cp.async helpers
// ---------------------------------------------------------------------------
__device__ __forceinline__ void cp16(float* s, const float* g) {
    unsigned sa = (unsigned)__cvta_generic_to_shared(s);
    asm volatile("cp.async.cg.shared.global [%0], [%1], 16;" :: "r"(sa), "l"(g));
}
__device__ __forceinline__ void cp_commit() {
    asm volatile("cp.async.commit_group;");
}
template <int N>
__device__ __forceinline__ void cp_wait() {
    asm volatile("cp.async.wait_group %0;" :: "n"(N));
}

// ---------------------------------------------------------------------------
// Main fused kernel. Grid: blockIdx.x = m*128 + bt  (expert-major -> L2 reuse)
// ---------------------------------------------------------------------------
__global__ void __launch_bounds__(THREADS, 1)
siren_main(const float* __restrict__ x,
           const float* __restrict__ w0, const float* __restrict__ b0,
           const float* __restrict__ b1, const float* __restrict__ b2,
           const float* __restrict__ b3,
           const float* __restrict__ wf, const float* __restrict__ bf,
           float* __restrict__ out) {
    extern __shared__ float smf[];
    float* hA = smf;                         // Hd * HPAD
    float* hB = hA + Hd * HPAD;              // Hd * HPAD
    float* wS = hB + Hd * HPAD;              // 2 * KT * Hd
    float* xT = wS + 2 * KT * Hd;            // BT * 4

    const int tid  = threadIdx.x;
    const int bt   = blockIdx.x & 127;
    const int m    = blockIdx.x >> 7;
    const int row0 = bt * BT;
    const int rx   = tid & 15;               // row group (4 rows each)
    const int ry   = tid >> 4;               // col group (16 cols each)

    // ---- stage x tile: xT[row*4 + c] ----
    if (tid < BT * INd) {
        int r = tid / INd, c = tid - r * INd;
        xT[r * 4 + c] = x[(row0 + r) * INd + c];
    }
    __syncthreads();

    // ---- layer 0: each thread owns one output feature o = tid ----
    {
        const int o = tid;
        const float* wp = w0 + ((size_t)m * Hd + o) * INd;
        const float a0 = wp[0], a1 = wp[1], a2 = wp[2];
        const float bb = b0[m * Hd + o];
        float* hd = hA + o * HPAD;
#pragma unroll 8
        for (int r = 0; r < BT; r++) {
            float v = fmaf(xT[r * 4 + 2], a2,
                      fmaf(xT[r * 4 + 1], a1,
                      fmaf(xT[r * 4 + 0], a0, bb)));
            hd[r] = __sinf(W0F * v);
        }
    }
    __syncthreads();

    // ---- 3 hidden layers: h_new[k2][r] = sin(30*(sum_k h[k][r]*wT[k][k2]+b))
    float* hsrc = hA;
    float* hdst = hB;
#pragma unroll
    for (int layer = 0; layer < 3; layer++) {
        const float* wt = &g_wT[layer][m][0][0];
        const float* bvec = (layer == 0) ? b1 : (layer == 1) ? b2 : b3;

        float acc[4][16];
#pragma unroll
        for (int i = 0; i < 4; i++)
#pragma unroll
            for (int j = 0; j < 16; j++) acc[i][j] = 0.0f;

        // prefetch chunk 0
        {
            const float* g = wt;
            float* s = wS;
#pragma unroll
            for (int t = 0; t < 8; t++)
                cp16(s + (tid + t * 256) * 4, g + (tid + t * 256) * 4);
            cp_commit();
        }

        for (int c = 0; c < NCHUNK; c++) {
            float* sbuf = wS + (c & 1) * (KT * Hd);
            if (c + 1 < NCHUNK) {
                const float* g = wt + (c + 1) * (KT * Hd);
                float* s = wS + ((c + 1) & 1) * (KT * Hd);
#pragma unroll
                for (int t = 0; t < 8; t++)
                    cp16(s + (tid + t * 256) * 4, g + (tid + t * 256) * 4);
                cp_commit();
                cp_wait<1>();
            } else {
                cp_wait<0>();
            }
            __syncthreads();

            const float* hk = hsrc + c * (KT * HPAD) + rx * 4;
#pragma unroll 4
            for (int k = 0; k < KT; k++) {
                const float4 a = *(const float4*)(hk + k * HPAD);
                const float* wrow = sbuf + k * Hd + ry * 16;
                const float4 wv0 = *(const float4*)(wrow + 0);
                const float4 wv1 = *(const float4*)(wrow + 4);
                const float4 wv2 = *(const float4*)(wrow + 8);
                const float4 wv3 = *(const float4*)(wrow + 12);
                float wreg[16];
                *(float4*)&wreg[0]  = wv0;
                *(float4*)&wreg[4]  = wv1;
                *(float4*)&wreg[8]  = wv2;
                *(float4*)&wreg[12] = wv3;
                float areg[4] = {a.x, a.y, a.z, a.w};
#pragma unroll
                for (int i = 0; i < 4; i++)
#pragma unroll
                    for (int j = 0; j < 16; j++)
                        acc[i][j] = fmaf(areg[i], wreg[j], acc[i][j]);
            }
            __syncthreads();   // protect sbuf before it is refilled at c+2
        }

        // epilogue: bias + sine, write transposed into hdst
        const float* bp = bvec + m * Hd + ry * 16;
#pragma unroll
        for (int j = 0; j < 16; j++) {
            const float bb = bp[j];
            float* hd = hdst + (ry * 16 + j) * HPAD + rx * 4;
#pragma unroll
            for (int i = 0; i < 4; i++)
                hd[i] = __sinf(W0F * (acc[i][j] + bb));
        }
        float* t = hsrc; hsrc = hdst; hdst = t;
        __syncthreads();
    }

    // ---- final linear: out[b,m,o] = h . wf[m,o,:] + bf[m,o] ----
    if (tid < BT * OUTd) {
        const int o = tid / BT;     // 0..2 (uniform within warp -> wf broadcast)
        const int r = tid - o * BT; // 0..63
        const float* wrow = wf + ((size_t)m * OUTd + o) * Hd;
        float acc = bf[m * OUTd + o];
#pragma unroll 8
        for (int k = 0; k < Hd; k++)
            acc = fmaf(hsrc[k * HPAD + r], wrow[k], acc);
        out[((size_t)(row0 + r) * Mexp + m) * OUTd + o] = acc;
    }
}

// ---------------------------------------------------------------------------
// Launch
// ---------------------------------------------------------------------------
extern "C" void kernel_launch(void* const* d_in, const int* in_sizes, int n_in,
                              void* d_out, int out_size) {
    (void)in_sizes; (void)n_in; (void)out_size;
    const float* x  = (const float*)d_in[0];
    const float* w0 = (const float*)d_in[1];
    const float* b0 = (const float*)d_in[2];
    const float* w1 = (const float*)d_in[3];
    const float* b1 = (const float*)d_in[4];
    const float* w2 = (const float*)d_in[5];
    const float* b2 = (const float*)d_in[6];
    const float* w3 = (const float*)d_in[7];
    const float* b3 = (const float*)d_in[8];
    const float* wf = (const float*)d_in[9];
    const float* bf = (const float*)d_in[10];
    float* out = (float*)d_out;

    cudaFuncSetAttribute(siren_main,
                         cudaFuncAttributeMaxDynamicSharedMemorySize, SMEM_BYTES);

    dim3 tb(32, 8);
    dim3 tg(Hd / 32, Hd / 32, Mexp);
    transpose_weights<<<tg, tb>>>(w1, 0);
    transpose_weights<<<tg, tb>>>(w2, 1);
    transpose_weights<<<tg, tb>>>(w3, 2);

    siren_main<<<Mexp * (Bdim / BT), THREADS, SMEM_BYTES>>>(
        x, w0, b0, b1, b2, b3, wf, bf, out);
}

// round 3
// speedup vs baseline: 2.7142x; 2.7142x over previous
#include <cuda_runtime.h>
#include <cuda_bf16.h>
#include <cstdint>

// ===========================================================================
// PackedSirenExperts via portable-PTX tensor cores (mma.sync m16n8k16 bf16).
// The harness PTX target is compute_103 (no 'a'), so tcgen05/TMEM are
// unavailable; HMMA via mma.sync is the fastest reachable tensor path.
//
// Per CTA: expert m, 128 batch rows. 8 warps = 4(m) x 2(n); warp owns a
// 32x128 C tile (128 fp32 acc regs). Activations in SMEM as bf16 hi/lo
// (swizzled), weights pre-split hi/lo + fragment-interleaved by prep kernel,
// streamed per-32k slab with cp.async double buffering.
// 3-term split: D += Ahi*Whi + Alo*Whi + Ahi*Wlo  (fp32 accumulate).
// ===========================================================================

namespace {
constexpr int Mexp = 64;
constexpr int Bdim = 8192;
constexpr float W0F = 30.0f;

constexpr int OFF_AHI  = 0;            // 128 x 256 bf16, swizzled (64 KB)
constexpr int OFF_ALO  = 65536;        // 64 KB
constexpr int OFF_WBUF = 131072;       // 2 x 40960 (256 rows x 160 B)
constexpr int WBUF_STRIDE = 40960;
constexpr int OFF_W0   = OFF_WBUF + 2 * WBUF_STRIDE;   // 212992: 768 f
constexpr int OFF_WF   = OFF_W0 + 3072;                // 768 f
constexpr int OFF_B0   = OFF_WF + 3072;                // 256 f
constexpr int OFF_B123 = OFF_B0 + 1024;                // 768 f
constexpr int OFF_X    = OFF_B123 + 3072;              // 384 f
constexpr int SMEM_TOTAL = OFF_X + 1536;               // 224768 B
}

// prepped weights: blob index = m*24 + layer*8 + slab; 32768 B each:
// 256 rows(o) x 128 B = [hi 64B | lo 64B], hi = (kk,q) 8B fragment words.
__device__ __align__(16) unsigned char g_wp[(size_t)Mexp * 24 * 32768];

// ---------------------------------------------------------------------------
__device__ __forceinline__ uint32_t smem_u32(const void* p) {
    uint32_t a;
    asm("{ .reg .u64 t; cvta.to.shared.u64 t, %1; cvt.u32.u64 %0, t; }" : "=r"(a) : "l"(p));
    return a;
}
__device__ __forceinline__ void cp16(uint32_t s, const void* g) {
    asm volatile("cp.async.cg.shared.global [%0], [%1], 16;" :: "r"(s), "l"(g));
}
__device__ __forceinline__ void cp_commit() { asm volatile("cp.async.commit_group;"); }
__device__ __forceinline__ void cp_wait0() {
    asm volatile("cp.async.wait_group 0;" ::: "memory");
}
__device__ __forceinline__ uint32_t pack2(float v0, float v1) {
    __nv_bfloat162 t = __floats2bfloat162_rn(v0, v1);
    return *reinterpret_cast<uint32_t*>(&t);
}
__device__ __forceinline__ uint32_t pack2lo(float v0, float v1) {
    __nv_bfloat16 h0 = __float2bfloat16(v0);
    __nv_bfloat16 h1 = __float2bfloat16(v1);
    __nv_bfloat162 t = __floats2bfloat162_rn(v0 - __bfloat162float(h0),
                                             v1 - __bfloat162float(h1));
    return *reinterpret_cast<uint32_t*>(&t);
}
// A swizzled byte offset: row r (0..127), col k (0..255) bf16
__device__ __forceinline__ uint32_t aoff(int r, int k) {
    return (uint32_t)(r * 512 + ((((k >> 3) ^ (r & 7)) << 4) | ((k & 7) * 2)));
}
__device__ __forceinline__ void mma16816(float* d, const uint32_t* a, const uint32_t* b) {
    asm volatile(
        "mma.sync.aligned.m16n8k16.row.col.f32.bf16.bf16.f32 "
        "{%0,%1,%2,%3}, {%4,%5,%6,%7}, {%8,%9}, {%0,%1,%2,%3};"
        : "+f"(d[0]), "+f"(d[1]), "+f"(d[2]), "+f"(d[3])
        : "r"(a[0]), "r"(a[1]), "r"(a[2]), "r"(a[3]), "r"(b[0]), "r"(b[1]));
}

// ---------------------------------------------------------------------------
// Prep: fp32 W[m][o][i] -> fragment-ready hi/lo bf16 blobs.
// thread -> (m, slab s, row n, q); writes both kk=0,1 hi+lo 8B words.
// ---------------------------------------------------------------------------
__global__ void prep_weights(const float* __restrict__ w, int layer) {
    int id = blockIdx.x * blockDim.x + threadIdx.x;   // 524288
    int m   = id >> 13;
    int s   = (id >> 10) & 7;
    int cid = id & 1023;
    int n   = cid >> 2;
    int q   = cid & 3;
    const float* src = w + ((size_t)m * 256 + n) * 256 + s * 32;
    unsigned char* dst = g_wp + ((size_t)(m * 24 + layer * 8 + s)) * 32768 + n * 128;
#pragma unroll
    for (int kk = 0; kk < 2; kk++) {
        int k0 = kk * 16 + q * 2;
        float f0 = src[k0], f1 = src[k0 + 1], f2 = src[k0 + 8], f3 = src[k0 + 9];
        uint2 hv, lv;
        hv.x = pack2(f0, f1);  hv.y = pack2(f2, f3);
        lv.x = pack2lo(f0, f1); lv.y = pack2lo(f2, f3);
        *reinterpret_cast<uint2*>(dst + kk * 32 + q * 8) = hv;
        *reinterpret_cast<uint2*>(dst + 64 + kk * 32 + q * 8) = lv;
    }
}

// ---------------------------------------------------------------------------
// Main kernel. grid = Mexp * 64 CTAs (expert-major), 256 threads.
// ---------------------------------------------------------------------------
__global__ void __launch_bounds__(256, 1)
siren_mma(const float* __restrict__ x,
          const float* __restrict__ w0, const float* __restrict__ b0,
          const float* __restrict__ b1, const float* __restrict__ b2,
          const float* __restrict__ b3,
          const float* __restrict__ wf, const float* __restrict__ bf,
          float* __restrict__ out) {
    extern __shared__ __align__(16) unsigned char smem[];
    const uint32_t sb = smem_u32(smem);
    float* w0s  = reinterpret_cast<float*>(smem + OFF_W0);
    float* wfs  = reinterpret_cast<float*>(smem + OFF_WF);
    float* b0s  = reinterpret_cast<float*>(smem + OFF_B0);
    float* b123 = reinterpret_cast<float*>(smem + OFF_B123);
    float* xs   = reinterpret_cast<float*>(smem + OFF_X);
    float* pbuf = reinterpret_cast<float*>(smem + OFF_WBUF);   // aliased, L2 epi only

    const int tid  = threadIdx.x;
    const int lane = tid & 31;
    const int wid  = tid >> 5;
    const int wm   = wid & 3;          // m-tile: rows wm*32..+31
    const int wn   = wid >> 2;         // n-half: cols wn*128..+127
    const int rl   = lane >> 2;        // 0..7
    const int q    = lane & 3;         // 0..3
    const int m    = blockIdx.x >> 6;
    const int bt   = blockIdx.x & 63;
    const int row0 = bt * 128;

    const unsigned char* wpm = g_wp + (size_t)m * 24 * 32768;

    // ---- prefetch slab 0 ----
    {
        const unsigned char* src = wpm;
        uint32_t dstb = sb + OFF_WBUF;
#pragma unroll
        for (int i = 0; i < 8; i++) {
            int id = tid + i * 256;
            int n = id >> 3, c = id & 7;
            cp16(dstb + n * 160 + c * 16, src + n * 128 + c * 16);
        }
        cp_commit();
    }

    // ---- stage small tensors ----
    for (int i = tid; i < 768; i += 256) w0s[i] = w0[m * 768 + i];
    for (int i = tid; i < 768; i += 256) wfs[i] = wf[m * 768 + i];
    if (tid < 256) {
        b0s[tid]        = b0[m * 256 + tid];
        b123[tid]       = b1[m * 256 + tid];
        b123[256 + tid] = b2[m * 256 + tid];
        b123[512 + tid] = b3[m * 256 + tid];
    }
    for (int i = tid; i < 384; i += 256) xs[i] = x[(size_t)row0 * 3 + i];
    __syncthreads();

    // ---- layer 0: per-warp region rows [wm*32,+32) x cols [wn*128,+128) ----
    {
        const int rbase = wm * 32, cbase = wn * 128;
#pragma unroll 4
        for (int i = 0; i < 64; i++) {
            int pid = lane + i * 32;
            int r = rbase + (pid >> 6);
            int c = cbase + (pid & 63) * 2;
            float x0 = xs[r * 3], x1 = xs[r * 3 + 1], x2 = xs[r * 3 + 2];
            float p0 = fmaf(x2, w0s[c * 3 + 2], fmaf(x1, w0s[c * 3 + 1],
                       fmaf(x0, w0s[c * 3 + 0], b0s[c])));
            float p1 = fmaf(x2, w0s[c * 3 + 5], fmaf(x1, w0s[c * 3 + 4],
                       fmaf(x0, w0s[c * 3 + 3], b0s[c + 1])));
            float v0 = __sinf(W0F * p0);
            float v1 = __sinf(W0F * p1);
            uint32_t ao = aoff(r, c);
            *reinterpret_cast<uint32_t*>(smem + OFF_AHI + ao) = pack2(v0, v1);
            *reinterpret_cast<uint32_t*>(smem + OFF_ALO + ao) = pack2lo(v0, v1);
        }
    }

    // ---- 3 hidden layers over 24 weight slabs ----
    int t = 0;
#pragma unroll 1
    for (int L = 0; L < 3; L++) {
        float acc[16][2][4];
#pragma unroll
        for (int n = 0; n < 16; n++)
#pragma unroll
            for (int f = 0; f < 2; f++)
#pragma unroll
                for (int v = 0; v < 4; v++) acc[n][f][v] = 0.0f;

#pragma unroll 1
        for (int s = 0; s < 8; s++, t++) {
            cp_wait0();
            __syncthreads();
            if (t < 23) {
                const unsigned char* src = wpm + (size_t)(t + 1) * 32768;
                uint32_t dstb = sb + OFF_WBUF + ((t + 1) & 1) * WBUF_STRIDE;
#pragma unroll
                for (int i = 0; i < 8; i++) {
                    int id = tid + i * 256;
                    int n = id >> 3, c = id & 7;
                    cp16(dstb + n * 160 + c * 16, src + n * 128 + c * 16);
                }
                cp_commit();
            }
            const unsigned char* wb = smem + OFF_WBUF + (t & 1) * WBUF_STRIDE;

#pragma unroll
            for (int kk = 0; kk < 2; kk++) {
                const int kg = s * 32 + kk * 16;
                uint32_t ah[2][4], al[2][4];
#pragma unroll
                for (int f = 0; f < 2; f++) {
                    int r = wm * 32 + f * 16 + rl;
                    uint32_t o00 = aoff(r,     kg + q * 2);
                    uint32_t o10 = aoff(r + 8, kg + q * 2);
                    uint32_t o01 = aoff(r,     kg + 8 + q * 2);
                    uint32_t o11 = aoff(r + 8, kg + 8 + q * 2);
                    ah[f][0] = *reinterpret_cast<const uint32_t*>(smem + OFF_AHI + o00);
                    ah[f][1] = *reinterpret_cast<const uint32_t*>(smem + OFF_AHI + o10);
                    ah[f][2] = *reinterpret_cast<const uint32_t*>(smem + OFF_AHI + o01);
                    ah[f][3] = *reinterpret_cast<const uint32_t*>(smem + OFF_AHI + o11);
                    al[f][0] = *reinterpret_cast<const uint32_t*>(smem + OFF_ALO + o00);
                    al[f][1] = *reinterpret_cast<const uint32_t*>(smem + OFF_ALO + o10);
                    al[f][2] = *reinterpret_cast<const uint32_t*>(smem + OFF_ALO + o01);
                    al[f][3] = *reinterpret_cast<const uint32_t*>(smem + OFF_ALO + o11);
                }
#pragma unroll
                for (int n = 0; n < 16; n++) {
                    int o = wn * 128 + n * 8 + rl;
                    const unsigned char* bp = wb + o * 160 + kk * 32 + q * 8;
                    uint2 bh = *reinterpret_cast<const uint2*>(bp);
                    uint2 bl = *reinterpret_cast<const uint2*>(bp + 64);
#pragma unroll
                    for (int f = 0; f < 2; f++) {
                        mma16816(acc[n][f], ah[f], &bh.x);
                        mma16816(acc[n][f], al[f], &bh.x);
                        mma16816(acc[n][f], ah[f], &bl.x);
                    }
                }
            }
        }

        __syncthreads();   // all warps done reading A for this layer

        if (L < 2) {
            const float* bl = b123 + L * 256;
#pragma unroll
            for (int n = 0; n < 16; n++) {
#pragma unroll
                for (int f = 0; f < 2; f++) {
                    int r   = wm * 32 + f * 16 + rl;
                    int col = wn * 128 + n * 8 + q * 2;
                    float bb0 = bl[col], bb1 = bl[col + 1];
                    float v0 = __sinf(W0F * (acc[n][f][0] + bb0));
                    float v1 = __sinf(W0F * (acc[n][f][1] + bb1));
                    float v2 = __sinf(W0F * (acc[n][f][2] + bb0));
                    float v3 = __sinf(W0F * (acc[n][f][3] + bb1));
                    uint32_t a0 = aoff(r, col);
                    uint32_t a1 = aoff(r + 8, col);
                    *reinterpret_cast<uint32_t*>(smem + OFF_AHI + a0) = pack2(v0, v1);
                    *reinterpret_cast<uint32_t*>(smem + OFF_ALO + a0) = pack2lo(v0, v1);
                    *reinterpret_cast<uint32_t*>(smem + OFF_AHI + a1) = pack2(v2, v3);
                    *reinterpret_cast<uint32_t*>(smem + OFF_ALO + a1) = pack2lo(v2, v3);
                }
            }
        } else {
            // final: sine + dot with wf (3 outputs), partial per n-half
            const float* bl = b123 + 512;
            float p[4][3];
#pragma unroll
            for (int i = 0; i < 4; i++)
#pragma unroll
                for (int o = 0; o < 3; o++) p[i][o] = 0.0f;
#pragma unroll
            for (int n = 0; n < 16; n++) {
#pragma unroll
                for (int f = 0; f < 2; f++) {
                    int col = wn * 128 + n * 8 + q * 2;
                    float bb0 = bl[col], bb1 = bl[col + 1];
                    float v0 = __sinf(W0F * (acc[n][f][0] + bb0));
                    float v1 = __sinf(W0F * (acc[n][f][1] + bb1));
                    float v2 = __sinf(W0F * (acc[n][f][2] + bb0));
                    float v3 = __sinf(W0F * (acc[n][f][3] + bb1));
#pragma unroll
                    for (int o = 0; o < 3; o++) {
                        float wf0 = wfs[o * 256 + col], wf1 = wfs[o * 256 + col + 1];
                        p[f * 2 + 0][o] = fmaf(v0, wf0, fmaf(v1, wf1, p[f * 2 + 0][o]));
                        p[f * 2 + 1][o] = fmaf(v2, wf0, fmaf(v3, wf1, p[f * 2 + 1][o]));
                    }
                }
            }
#pragma unroll
            for (int i = 0; i < 4; i++)
#pragma unroll
                for (int o = 0; o < 3; o++) {
                    p[i][o] += __shfl_xor_sync(0xffffffffu, p[i][o], 1);
                    p[i][o] += __shfl_xor_sync(0xffffffffu, p[i][o], 2);
                }
            if (q == 0) {
#pragma unroll
                for (int f = 0; f < 2; f++)
#pragma unroll
                    for (int pr = 0; pr < 2; pr++) {
                        int rloc = wm * 32 + f * 16 + rl + pr * 8;
#pragma unroll
                        for (int o = 0; o < 3; o++)
                            pbuf[wn * 384 + rloc * 3 + o] = p[f * 2 + pr][o];
                    }
            }
            __syncthreads();
            for (int i = tid; i < 384; i += 256) {
                int r = i / 3, o = i - r * 3;
                float v = pbuf[i] + pbuf[384 + i] + bf[m * 3 + o];
                out[((size_t)(row0 + r) * Mexp + m) * 3 + o] = v;
            }
        }
    }
}

// ---------------------------------------------------------------------------
extern "C" void kernel_launch(void* const* d_in, const int* in_sizes, int n_in,
                              void* d_out, int out_size) {
    (void)in_sizes; (void)n_in; (void)out_size;
    const float* x  = (const float*)d_in[0];
    const float* w0 = (const float*)d_in[1];
    const float* b0 = (const float*)d_in[2];
    const float* w1 = (const float*)d_in[3];
    const float* b1 = (const float*)d_in[4];
    const float* w2 = (const float*)d_in[5];
    const float* b2 = (const float*)d_in[6];
    const float* w3 = (const float*)d_in[7];
    const float* b3 = (const float*)d_in[8];
    const float* wf = (const float*)d_in[9];
    const float* bf = (const float*)d_in[10];
    float* out = (float*)d_out;

    cudaFuncSetAttribute(siren_mma, cudaFuncAttributeMaxDynamicSharedMemorySize,
                         SMEM_TOTAL);

    prep_weights<<<2048, 256>>>(w1, 0);
    prep_weights<<<2048, 256>>>(w2, 1);
    prep_weights<<<2048, 256>>>(w3, 2);

    siren_mma<<<Mexp * (Bdim / 128), 256, SMEM_TOTAL>>>(
        x, w0, b0, b1, b2, b3, wf, bf, out);
}

// round 4
// speedup vs baseline: 3.0494x; 1.1235x over previous
#include <cuda_runtime.h>
#include <cuda_bf16.h>
#include <cstdint>

// ===========================================================================
// PackedSirenExperts via mma.sync m16n8k16 bf16 (portable PTX for compute_103).
// R4: 2 CTAs/SM. CTA = (expert, 64 rows), 128 threads, 4 warps = 2m x 2n,
// warp tile 32x128 (128 fp32 acc regs). SMEM 109.3 KB/CTA.
// 3-term bf16 split: D += Ahi*Whi + Alo*Whi + Ahi*Wlo (fp32 accum).
// Weights pre-split/fragment-packed into 16KB k16-slabs (hi 8K | lo 8K,
// 32B rows -> conflict-free LDS.64 B fragments), cp.async double buffered.
// ===========================================================================

namespace {
constexpr int Mexp = 64;
constexpr int Bdim = 8192;
constexpr float W0F = 30.0f;

constexpr int OFF_AHI  = 0;          // 64 rows x 512B (swizzled bf16)  32K
constexpr int OFF_ALO  = 32768;      // 32K
constexpr int OFF_WBUF = 65536;      // 2 x 16384
constexpr int OFF_W0   = 98304;      // 768 f
constexpr int OFF_WF   = 101376;     // 768 f
constexpr int OFF_B0   = 104448;     // 256 f
constexpr int OFF_B123 = 105472;     // 768 f
constexpr int OFF_X    = 108544;     // 192 f
constexpr int SMEM_TOTAL = 109312;
}

// prepped weights: blob = [m][layer*16 + slab] of 16KB:
//   [hi: 256 o-rows x 32B][lo: 256 x 32B]; row = 4 q-words (uint2):
//   {bf16x2(k=2q,2q+1), bf16x2(k=2q+8,2q+9)} for k within the 16-wide slab.
__device__ __align__(16) unsigned char g_wp[(size_t)Mexp * 48 * 16384];

// ---------------------------------------------------------------------------
__device__ __forceinline__ uint32_t smem_u32(const void* p) {
    uint32_t a;
    asm("{ .reg .u64 t; cvta.to.shared.u64 t, %1; cvt.u32.u64 %0, t; }" : "=r"(a) : "l"(p));
    return a;
}
__device__ __forceinline__ void cp16(uint32_t s, const void* g) {
    asm volatile("cp.async.cg.shared.global [%0], [%1], 16;" :: "r"(s), "l"(g));
}
__device__ __forceinline__ void cp_commit() { asm volatile("cp.async.commit_group;"); }
__device__ __forceinline__ void cp_wait0() {
    asm volatile("cp.async.wait_group 0;" ::: "memory");
}
__device__ __forceinline__ uint32_t pack2(float v0, float v1) {
    __nv_bfloat162 t = __floats2bfloat162_rn(v0, v1);
    return *reinterpret_cast<uint32_t*>(&t);
}
__device__ __forceinline__ uint32_t pack2lo(float v0, float v1) {
    __nv_bfloat16 h0 = __float2bfloat16(v0);
    __nv_bfloat16 h1 = __float2bfloat16(v1);
    __nv_bfloat162 t = __floats2bfloat162_rn(v0 - __bfloat162float(h0),
                                             v1 - __bfloat162float(h1));
    return *reinterpret_cast<uint32_t*>(&t);
}
// A swizzled byte offset: row r (0..63), col k (0..255) bf16
__device__ __forceinline__ uint32_t aoff(int r, int k) {
    return (uint32_t)(r * 512 + ((((k >> 3) ^ (r & 7)) << 4) | ((k & 7) * 2)));
}
__device__ __forceinline__ void mma16816(float* d, const uint32_t* a, const uint32_t* b) {
    asm volatile(
        "mma.sync.aligned.m16n8k16.row.col.f32.bf16.bf16.f32 "
        "{%0,%1,%2,%3}, {%4,%5,%6,%7}, {%8,%9}, {%0,%1,%2,%3};"
        : "+f"(d[0]), "+f"(d[1]), "+f"(d[2]), "+f"(d[3])
        : "r"(a[0]), "r"(a[1]), "r"(a[2]), "r"(a[3]), "r"(b[0]), "r"(b[1]));
}

// ---------------------------------------------------------------------------
// Prep: fp32 W[m][o][i] -> k16-slab blobs. One thread per (m, slab, o-row).
// ---------------------------------------------------------------------------
__global__ void prep_weights(const float* __restrict__ w, int layer) {
    int id = blockIdx.x * blockDim.x + threadIdx.x;   // 262144
    int o = id & 255;
    int s = (id >> 8) & 15;
    int m = id >> 12;
    const float* src = w + ((size_t)m * 256 + o) * 256 + s * 16;
    unsigned char* dst = g_wp + (size_t)(m * 48 + layer * 16 + s) * 16384 + o * 32;
#pragma unroll
    for (int q = 0; q < 4; q++) {
        float f0 = src[2 * q],     f1 = src[2 * q + 1];
        float f2 = src[2 * q + 8], f3 = src[2 * q + 9];
        uint2 hv, lv;
        hv.x = pack2(f0, f1);   hv.y = pack2(f2, f3);
        lv.x = pack2lo(f0, f1); lv.y = pack2lo(f2, f3);
        *reinterpret_cast<uint2*>(dst + q * 8) = hv;
        *reinterpret_cast<uint2*>(dst + 8192 + q * 8) = lv;
    }
}

// ---------------------------------------------------------------------------
// Main kernel. grid = Mexp*128 = 8192 CTAs (expert-major), 128 threads.
// ---------------------------------------------------------------------------
__global__ void __launch_bounds__(128, 2)
siren_mma(const float* __restrict__ x,
          const float* __restrict__ w0, const float* __restrict__ b0,
          const float* __restrict__ b1, const float* __restrict__ b2,
          const float* __restrict__ b3,
          const float* __restrict__ wf, const float* __restrict__ bf,
          float* __restrict__ out) {
    extern __shared__ __align__(16) unsigned char smem[];
    const uint32_t sb = smem_u32(smem);
    float* w0s  = reinterpret_cast<float*>(smem + OFF_W0);
    float* wfs  = reinterpret_cast<float*>(smem + OFF_WF);
    float* b0s  = reinterpret_cast<float*>(smem + OFF_B0);
    float* b123 = reinterpret_cast<float*>(smem + OFF_B123);
    float* xs   = reinterpret_cast<float*>(smem + OFF_X);
    float* pbuf = reinterpret_cast<float*>(smem + OFF_WBUF);   // aliased: final epi only

    const int tid  = threadIdx.x;
    const int lane = tid & 31;
    const int wid  = tid >> 5;
    const int wm   = wid & 1;          // m-tile: rows wm*32..+31
    const int wn   = wid >> 1;         // n-half: cols wn*128..+127
    const int rl   = lane >> 2;        // 0..7
    const int q    = lane & 3;         // 0..3
    const int m    = blockIdx.x >> 7;
    const int bt   = blockIdx.x & 127;
    const int row0 = bt * 64;

    const unsigned char* wpm = g_wp + (size_t)m * 48 * 16384;

    // ---- prefetch slab 0 ----
    {
        uint32_t dstb = sb + OFF_WBUF + tid * 16;
        const unsigned char* src = wpm + tid * 16;
#pragma unroll
        for (int i = 0; i < 8; i++) cp16(dstb + i * 2048, src + i * 2048);
        cp_commit();
    }

    // ---- stage small tensors ----
    for (int i = tid; i < 768; i += 128) w0s[i] = w0[m * 768 + i];
    for (int i = tid; i < 768; i += 128) wfs[i] = wf[m * 768 + i];
    for (int i = tid; i < 256; i += 128) {
        b0s[i]        = b0[m * 256 + i];
        b123[i]       = b1[m * 256 + i];
        b123[256 + i] = b2[m * 256 + i];
        b123[512 + i] = b3[m * 256 + i];
    }
    for (int i = tid; i < 192; i += 128) xs[i] = x[(size_t)row0 * 3 + i];
    __syncthreads();

    // ---- layer 0: per-warp region rows [wm*32,+32) x cols [wn*128,+128) ----
    {
        const int rbase = wm * 32, cbase = wn * 128;
#pragma unroll 4
        for (int i = 0; i < 64; i++) {
            int pid = lane + i * 32;
            int r = rbase + (pid >> 6);
            int c = cbase + (pid & 63) * 2;
            float x0 = xs[r * 3], x1 = xs[r * 3 + 1], x2 = xs[r * 3 + 2];
            float p0 = fmaf(x2, w0s[c * 3 + 2], fmaf(x1, w0s[c * 3 + 1],
                       fmaf(x0, w0s[c * 3 + 0], b0s[c])));
            float p1 = fmaf(x2, w0s[c * 3 + 5], fmaf(x1, w0s[c * 3 + 4],
                       fmaf(x0, w0s[c * 3 + 3], b0s[c + 1])));
            float v0 = __sinf(W0F * p0);
            float v1 = __sinf(W0F * p1);
            uint32_t ao = aoff(r, c);
            *reinterpret_cast<uint32_t*>(smem + OFF_AHI + ao) = pack2(v0, v1);
            *reinterpret_cast<uint32_t*>(smem + OFF_ALO + ao) = pack2lo(v0, v1);
        }
    }

    // ---- 3 hidden layers over 48 k16 weight slabs ----
    int t = 0;
#pragma unroll 1
    for (int L = 0; L < 3; L++) {
        float acc[16][2][4];
#pragma unroll
        for (int n = 0; n < 16; n++)
#pragma unroll
            for (int f = 0; f < 2; f++)
#pragma unroll
                for (int v = 0; v < 4; v++) acc[n][f][v] = 0.0f;

#pragma unroll 1
        for (int s = 0; s < 16; s++, t++) {
            cp_wait0();
            __syncthreads();
            if (t < 47) {
                uint32_t dstb = sb + OFF_WBUF + ((t + 1) & 1) * 16384 + tid * 16;
                const unsigned char* src = wpm + (size_t)(t + 1) * 16384 + tid * 16;
#pragma unroll
                for (int i = 0; i < 8; i++) cp16(dstb + i * 2048, src + i * 2048);
                cp_commit();
            }
            const unsigned char* wb = smem + OFF_WBUF + (t & 1) * 16384;
            const int kg = s * 16;

            uint32_t ah[2][4], al[2][4];
#pragma unroll
            for (int f = 0; f < 2; f++) {
                int r = wm * 32 + f * 16 + rl;
                uint32_t o00 = aoff(r,     kg + q * 2);
                uint32_t o10 = aoff(r + 8, kg + q * 2);
                uint32_t o01 = aoff(r,     kg + 8 + q * 2);
                uint32_t o11 = aoff(r + 8, kg + 8 + q * 2);
                ah[f][0] = *reinterpret_cast<const uint32_t*>(smem + OFF_AHI + o00);
                ah[f][1] = *reinterpret_cast<const uint32_t*>(smem + OFF_AHI + o10);
                ah[f][2] = *reinterpret_cast<const uint32_t*>(smem + OFF_AHI + o01);
                ah[f][3] = *reinterpret_cast<const uint32_t*>(smem + OFF_AHI + o11);
                al[f][0] = *reinterpret_cast<const uint32_t*>(smem + OFF_ALO + o00);
                al[f][1] = *reinterpret_cast<const uint32_t*>(smem + OFF_ALO + o10);
                al[f][2] = *reinterpret_cast<const uint32_t*>(smem + OFF_ALO + o01);
                al[f][3] = *reinterpret_cast<const uint32_t*>(smem + OFF_ALO + o11);
            }
#pragma unroll
            for (int n = 0; n < 16; n++) {
                int o = wn * 128 + n * 8 + rl;
                uint2 bh = *reinterpret_cast<const uint2*>(wb + o * 32 + q * 8);
                uint2 bl = *reinterpret_cast<const uint2*>(wb + 8192 + o * 32 + q * 8);
#pragma unroll
                for (int f = 0; f < 2; f++) {
                    mma16816(acc[n][f], ah[f], &bh.x);
                    mma16816(acc[n][f], al[f], &bh.x);
                    mma16816(acc[n][f], ah[f], &bl.x);
                }
            }
        }

        __syncthreads();   // all warps done reading A for this layer

        if (L < 2) {
            const float* bl = b123 + L * 256;
#pragma unroll
            for (int n = 0; n < 16; n++) {
#pragma unroll
                for (int f = 0; f < 2; f++) {
                    int r   = wm * 32 + f * 16 + rl;
                    int col = wn * 128 + n * 8 + q * 2;
                    float bb0 = bl[col], bb1 = bl[col + 1];
                    float v0 = __sinf(W0F * (acc[n][f][0] + bb0));
                    float v1 = __sinf(W0F * (acc[n][f][1] + bb1));
                    float v2 = __sinf(W0F * (acc[n][f][2] + bb0));
                    float v3 = __sinf(W0F * (acc[n][f][3] + bb1));
                    uint32_t a0 = aoff(r, col);
                    uint32_t a1 = aoff(r + 8, col);
                    *reinterpret_cast<uint32_t*>(smem + OFF_AHI + a0) = pack2(v0, v1);
                    *reinterpret_cast<uint32_t*>(smem + OFF_ALO + a0) = pack2lo(v0, v1);
                    *reinterpret_cast<uint32_t*>(smem + OFF_AHI + a1) = pack2(v2, v3);
                    *reinterpret_cast<uint32_t*>(smem + OFF_ALO + a1) = pack2lo(v2, v3);
                }
            }
        } else {
            // final: sine + dot with wf (3 outputs), partial per n-half
            const float* bl = b123 + 512;
            float p[4][3];
#pragma unroll
            for (int i = 0; i < 4; i++)
#pragma unroll
                for (int o = 0; o < 3; o++) p[i][o] = 0.0f;
#pragma unroll
            for (int n = 0; n < 16; n++) {
#pragma unroll
                for (int f = 0; f < 2; f++) {
                    int col = wn * 128 + n * 8 + q * 2;
                    float bb0 = bl[col], bb1 = bl[col + 1];
                    float v0 = __sinf(W0F * (acc[n][f][0] + bb0));
                    float v1 = __sinf(W0F * (acc[n][f][1] + bb1));
                    float v2 = __sinf(W0F * (acc[n][f][2] + bb0));
                    float v3 = __sinf(W0F * (acc[n][f][3] + bb1));
#pragma unroll
                    for (int o = 0; o < 3; o++) {
                        float wf0 = wfs[o * 256 + col], wf1 = wfs[o * 256 + col + 1];
                        p[f * 2 + 0][o] = fmaf(v0, wf0, fmaf(v1, wf1, p[f * 2 + 0][o]));
                        p[f * 2 + 1][o] = fmaf(v2, wf0, fmaf(v3, wf1, p[f * 2 + 1][o]));
                    }
                }
            }
#pragma unroll
            for (int i = 0; i < 4; i++)
#pragma unroll
                for (int o = 0; o < 3; o++) {
                    p[i][o] += __shfl_xor_sync(0xffffffffu, p[i][o], 1);
                    p[i][o] += __shfl_xor_sync(0xffffffffu, p[i][o], 2);
                }
            if (q == 0) {
#pragma unroll
                for (int f = 0; f < 2; f++)
#pragma unroll
                    for (int pr = 0; pr < 2; pr++) {
                        int rloc = wm * 32 + f * 16 + rl + pr * 8;
#pragma unroll
                        for (int o = 0; o < 3; o++)
                            pbuf[wn * 192 + rloc * 3 + o] = p[f * 2 + pr][o];
                    }
            }
            __syncthreads();
            for (int i = tid; i < 192; i += 128) {
                int r = i / 3, o = i - r * 3;
                float v = pbuf[i] + pbuf[192 + i] + bf[m * 3 + o];
                out[((size_t)(row0 + r) * Mexp + m) * 3 + o] = v;
            }
        }
    }
}

// ---------------------------------------------------------------------------
extern "C" void kernel_launch(void* const* d_in, const int* in_sizes, int n_in,
                              void* d_out, int out_size) {
    (void)in_sizes; (void)n_in; (void)out_size;
    const float* x  = (const float*)d_in[0];
    const float* w0 = (const float*)d_in[1];
    const float* b0 = (const float*)d_in[2];
    const float* w1 = (const float*)d_in[3];
    const float* b1 = (const float*)d_in[4];
    const float* w2 = (const float*)d_in[5];
    const float* b2 = (const float*)d_in[6];
    const float* w3 = (const float*)d_in[7];
    const float* b3 = (const float*)d_in[8];
    const float* wf = (const float*)d_in[9];
    const float* bf = (const float*)d_in[10];
    float* out = (float*)d_out;

    cudaFuncSetAttribute(siren_mma, cudaFuncAttributeMaxDynamicSharedMemorySize,
                         SMEM_TOTAL);

    prep_weights<<<1024, 256>>>(w1, 0);
    prep_weights<<<1024, 256>>>(w2, 1);
    prep_weights<<<1024, 256>>>(w3, 2);

    siren_mma<<<Mexp * (Bdim / 64), 128, SMEM_TOTAL>>>(
        x, w0, b0, b1, b2, b3, wf, bf, out);
}